// round 2
// baseline (speedup 1.0000x reference)
#include <cuda_runtime.h>

#define CC   128
#define HH   2
#define HC   256
#define NMAX 100000
#define EMAX 1600000

// ---------------- device scratch (static, no allocation) ----------------
__device__ float g_q[(size_t)NMAX * HC];      // normalized qs, [n][h][c]
__device__ float g_k[(size_t)NMAX * HC];      // normalized ks
__device__ float g_bufA[(size_t)NMAX * HC];   // term ping
__device__ float g_bufB[(size_t)NMAX * HC];   // term pong
__device__ float g_deginv[NMAX];
__device__ int   g_deg[NMAX];
__device__ int   g_csroff[NMAX + 1];
__device__ int   g_csrcur[NMAX];
__device__ int   g_csrrow[EMAX];
__device__ float g_den[NMAX * HH];
__device__ float g_kvs[HH * CC * CC];
__device__ float g_vssum[HH * CC];
__device__ float g_kssum[HH * CC];
__device__ int   g_is64;

// ---------------- edge dtype detection ----------------
// If edge_index is int64 (little-endian, values < 2^31), every odd int32 word
// is zero. If it's int32, odd words are random node ids (~never all zero).
__global__ void detect_dtype_kernel(const int* __restrict__ ei32, int twoE) {
    __shared__ int nz;
    if (threadIdx.x == 0) nz = 0;
    __syncthreads();
    int samples = min(1024, twoE / 2);
    int local = 0;
    for (int i = threadIdx.x; i < samples; i += blockDim.x)
        if (ei32[2 * i + 1] != 0) local++;
    if (local) atomicAdd(&nz, local);
    __syncthreads();
    if (threadIdx.x == 0) g_is64 = (nz == 0) ? 1 : 0;
}

__device__ __forceinline__ int edge_col(const void* ei, int E, int e) {
    if (g_is64) return (int)((const long long*)ei)[(size_t)E + e];
    return ((const int*)ei)[E + e];
}
__device__ __forceinline__ int edge_row(const void* ei, int E, int e) {
    if (g_is64) return (int)((const long long*)ei)[e];
    return ((const int*)ei)[e];
}

// ---------------- edge prep ----------------
__global__ void edge_deg_kernel(const void* __restrict__ ei, int E) {
    int e = blockIdx.x * blockDim.x + threadIdx.x;
    if (e < E) {
        int c = edge_col(ei, E, e);
        atomicAdd(&g_deg[c], 1);
    }
}

__global__ void scan_kernel(int n, int E) {
    __shared__ int sh[1024];
    __shared__ int carrySh;
    if (threadIdx.x == 0) carrySh = 0;
    __syncthreads();
    for (int base = 0; base < n; base += 1024) {
        int i = base + threadIdx.x;
        int v = (i < n) ? g_deg[i] : 0;
        sh[threadIdx.x] = v;
        __syncthreads();
        for (int off = 1; off < 1024; off <<= 1) {
            int t = (threadIdx.x >= off) ? sh[threadIdx.x - off] : 0;
            __syncthreads();
            sh[threadIdx.x] += t;
            __syncthreads();
        }
        int excl = sh[threadIdx.x] - v + carrySh;
        if (i < n) {
            g_csroff[i] = excl;
            g_csrcur[i] = excl;
            g_deginv[i] = (v > 0) ? 1.0f / (float)v : 0.0f;
        }
        __syncthreads();
        if (threadIdx.x == 0) carrySh += sh[1023];
        __syncthreads();
    }
    if (threadIdx.x == 0) g_csroff[n] = E;
}

__global__ void csr_scatter_kernel(const void* __restrict__ ei, int E) {
    int e = blockIdx.x * blockDim.x + threadIdx.x;
    if (e < E) {
        int c = edge_col(ei, E, e);
        int pos = atomicAdd(&g_csrcur[c], 1);
        g_csrrow[pos] = edge_row(ei, E, e);
    }
}

// ---------------- q/k projection GEMM: [N,128] @ [128,512] ----------------
// grid.y in 0..3: 0,1 -> q halves; 2,3 -> k halves. Writes un-normalized.
__global__ void qk_gemm_kernel(const float* __restrict__ x,
                               const float* __restrict__ Wq, const float* __restrict__ Wqb,
                               const float* __restrict__ Wk, const float* __restrict__ Wkb,
                               int n) {
    __shared__ float As[16][128];
    __shared__ float Bs[16][128];
    int t = threadIdx.x;
    int bm0 = blockIdx.x * 128;
    int by = blockIdx.y;
    const float* B   = (by < 2) ? Wq  : Wk;
    const float* bia = (by < 2) ? Wqb : Wkb;
    float*       dst = (by < 2) ? g_q : g_k;
    int coff = (by & 1) * 128;
    int am = t >> 1, akq = (t & 1) * 8;
    int bk = t >> 4, bnq = (t & 15) * 8;
    int tm = (t >> 4) * 8, tn = (t & 15) * 8;
    float acc[8][8];
#pragma unroll
    for (int i = 0; i < 8; i++)
#pragma unroll
        for (int j = 0; j < 8; j++) acc[i][j] = 0.f;

    for (int k0 = 0; k0 < 128; k0 += 16) {
        float4 a0 = make_float4(0, 0, 0, 0), a1 = a0;
        int row = bm0 + am;
        if (row < n) {
            const float4* ap = (const float4*)(x + (size_t)row * 128 + k0 + akq);
            a0 = ap[0]; a1 = ap[1];
        }
        const float4* bp = (const float4*)(B + (size_t)(k0 + bk) * 256 + coff + bnq);
        float4 b0 = bp[0], b1 = bp[1];
        __syncthreads();
        As[akq + 0][am] = a0.x; As[akq + 1][am] = a0.y;
        As[akq + 2][am] = a0.z; As[akq + 3][am] = a0.w;
        As[akq + 4][am] = a1.x; As[akq + 5][am] = a1.y;
        As[akq + 6][am] = a1.z; As[akq + 7][am] = a1.w;
        *(float4*)&Bs[bk][bnq]     = b0;
        *(float4*)&Bs[bk][bnq + 4] = b1;
        __syncthreads();
#pragma unroll
        for (int kk = 0; kk < 16; kk++) {
            float a[8], b[8];
#pragma unroll
            for (int i = 0; i < 8; i++) a[i] = As[kk][tm + i];
#pragma unroll
            for (int j = 0; j < 8; j++) b[j] = Bs[kk][tn + j];
#pragma unroll
            for (int i = 0; i < 8; i++)
#pragma unroll
                for (int j = 0; j < 8; j++) acc[i][j] += a[i] * b[j];
        }
    }
#pragma unroll
    for (int i = 0; i < 8; i++) {
        int row = bm0 + tm + i;
        if (row >= n) break;
        float4 o0, o1;
        o0.x = acc[i][0] + bia[coff + tn + 0];
        o0.y = acc[i][1] + bia[coff + tn + 1];
        o0.z = acc[i][2] + bia[coff + tn + 2];
        o0.w = acc[i][3] + bia[coff + tn + 3];
        o1.x = acc[i][4] + bia[coff + tn + 4];
        o1.y = acc[i][5] + bia[coff + tn + 5];
        o1.z = acc[i][6] + bia[coff + tn + 6];
        o1.w = acc[i][7] + bia[coff + tn + 7];
        *(float4*)&dst[(size_t)row * 256 + coff + tn]     = o0;
        *(float4*)&dst[(size_t)row * 256 + coff + tn + 4] = o1;
    }
}

// ---------------- per-(node,head) L2 normalize (q and k) ----------------
__global__ void normalize_kernel(int n) {
    int gw = (blockIdx.x * blockDim.x + threadIdx.x) >> 5;
    int lane = threadIdx.x & 31;
    if (gw >= n * 4) return;
    int node = gw >> 2, sel = gw & 3;
    float* base = ((sel < 2) ? g_q : g_k) + (size_t)node * 256 + (sel & 1) * 128;
    float4 v = ((float4*)base)[lane];
    float ss = v.x * v.x + v.y * v.y + v.z * v.z + v.w * v.w;
#pragma unroll
    for (int o = 16; o; o >>= 1) ss += __shfl_xor_sync(0xffffffffu, ss, o);
    float inv = rsqrtf(ss);
    v.x *= inv; v.y *= inv; v.z *= inv; v.w *= inv;
    ((float4*)base)[lane] = v;
}

// ---------------- ks_sum (loop-invariant) ----------------
__global__ void kssum_kernel(int n) {
    int col = threadIdx.x;  // 0..255 == h*128+c
    int start = blockIdx.x * 512;
    int end = min(start + 512, n);
    float s = 0.f;
    for (int node = start; node < end; node++) s += g_k[(size_t)node * 256 + col];
    atomicAdd(&g_kssum[col], s);
}

// ---------------- den = qs . ks_sum + n (loop-invariant) ----------------
__global__ void den_kernel(int n) {
    int gw = (blockIdx.x * blockDim.x + threadIdx.x) >> 5;
    int lane = threadIdx.x & 31;
    if (gw >= n * 2) return;
    int node = gw >> 1, h = gw & 1;
    float4 qv = ((const float4*)(g_q + (size_t)node * 256 + h * 128))[lane];
    float4 kv = ((const float4*)(g_kssum + h * 128))[lane];
    float d = qv.x * kv.x + qv.y * kv.y + qv.z * kv.z + qv.w * kv.w;
#pragma unroll
    for (int o = 16; o; o >>= 1) d += __shfl_xor_sync(0xffffffffu, d, o);
    if (lane == 0) g_den[node * 2 + h] = d + (float)n;
}

// ---------------- term0 = broadcast x over heads ----------------
__global__ void broadcast_kernel(const float* __restrict__ x, int n) {
    int idx = blockIdx.x * blockDim.x + threadIdx.x;
    if (idx < n * 256) {
        int node = idx >> 8;
        int c = idx & 127;
        g_bufA[idx] = x[(size_t)node * 128 + c];
    }
}

// ---------------- out init: 0.5*(x @ (Wo[h0,k=0]+Wo[h1,k=0]) + b) ----------------
__global__ void out_init_kernel(const float* __restrict__ x, const float* __restrict__ Wo,
                                const float* __restrict__ Wob, float* __restrict__ out, int n) {
    __shared__ float As[16][128];
    __shared__ float Bs[16][128];
    int t = threadIdx.x;
    int bm0 = blockIdx.x * 128;
    int am = t >> 1, akq = (t & 1) * 8;
    int bk = t >> 4, bnq = (t & 15) * 8;
    int tm = (t >> 4) * 8, tn = (t & 15) * 8;
    float acc[8][8];
#pragma unroll
    for (int i = 0; i < 8; i++)
#pragma unroll
        for (int j = 0; j < 8; j++) acc[i][j] = 0.f;

    for (int k0 = 0; k0 < 128; k0 += 16) {
        float4 a0 = make_float4(0, 0, 0, 0), a1 = a0;
        int row = bm0 + am;
        if (row < n) {
            const float4* ap = (const float4*)(x + (size_t)row * 128 + k0 + akq);
            a0 = ap[0]; a1 = ap[1];
        }
        int wr = k0 + bk;
        const float4* p0 = (const float4*)(Wo + (size_t)wr * 128 + bnq);
        const float4* p1 = (const float4*)(Wo + (size_t)(640 + wr) * 128 + bnq);
        float4 u0 = p0[0], u1 = p0[1], v0 = p1[0], v1 = p1[1];
        float4 b0, b1;
        b0.x = u0.x + v0.x; b0.y = u0.y + v0.y; b0.z = u0.z + v0.z; b0.w = u0.w + v0.w;
        b1.x = u1.x + v1.x; b1.y = u1.y + v1.y; b1.z = u1.z + v1.z; b1.w = u1.w + v1.w;
        __syncthreads();
        As[akq + 0][am] = a0.x; As[akq + 1][am] = a0.y;
        As[akq + 2][am] = a0.z; As[akq + 3][am] = a0.w;
        As[akq + 4][am] = a1.x; As[akq + 5][am] = a1.y;
        As[akq + 6][am] = a1.z; As[akq + 7][am] = a1.w;
        *(float4*)&Bs[bk][bnq]     = b0;
        *(float4*)&Bs[bk][bnq + 4] = b1;
        __syncthreads();
#pragma unroll
        for (int kk = 0; kk < 16; kk++) {
            float a[8], b[8];
#pragma unroll
            for (int i = 0; i < 8; i++) a[i] = As[kk][tm + i];
#pragma unroll
            for (int j = 0; j < 8; j++) b[j] = Bs[kk][tn + j];
#pragma unroll
            for (int i = 0; i < 8; i++)
#pragma unroll
                for (int j = 0; j < 8; j++) acc[i][j] += a[i] * b[j];
        }
    }
#pragma unroll
    for (int i = 0; i < 8; i++) {
        int row = bm0 + tm + i;
        if (row >= n) break;
        float4 o0, o1;
        o0.x = 0.5f * (acc[i][0] + Wob[tn + 0]);
        o0.y = 0.5f * (acc[i][1] + Wob[tn + 1]);
        o0.z = 0.5f * (acc[i][2] + Wob[tn + 2]);
        o0.w = 0.5f * (acc[i][3] + Wob[tn + 3]);
        o1.x = 0.5f * (acc[i][4] + Wob[tn + 4]);
        o1.y = 0.5f * (acc[i][5] + Wob[tn + 5]);
        o1.z = 0.5f * (acc[i][6] + Wob[tn + 6]);
        o1.w = 0.5f * (acc[i][7] + Wob[tn + 7]);
        *(float4*)&out[(size_t)row * 128 + tn]     = o0;
        *(float4*)&out[(size_t)row * 128 + tn + 4] = o1;
    }
}

// ---------------- kvs[h] += ks_chunk^T @ prev_chunk ; vs_sum partials ----------------
__global__ void kvs_reduce_kernel(const float* __restrict__ prev, int n) {
    int h = blockIdx.y;
    int c0 = blockIdx.x * 512;
    int c1 = min(c0 + 512, n);
    __shared__ float ksS[16][128];
    __shared__ float pvS[16][128];
    int t = threadIdx.x;
    int ln = t >> 4;
    int cq = (t & 15) * 8;
    int tm = (t >> 4) * 8, tn = (t & 15) * 8;
    float acc[8][8];
#pragma unroll
    for (int i = 0; i < 8; i++)
#pragma unroll
        for (int j = 0; j < 8; j++) acc[i][j] = 0.f;
    float colsum = 0.f;
    int myc = t & 127, rb = (t >> 7) * 8;

    for (int s = c0; s < c1; s += 16) {
        int node = s + ln;
        float4 z = make_float4(0, 0, 0, 0);
        float4 k0 = z, k1 = z, p0 = z, p1 = z;
        if (node < c1) {
            const float4* kp = (const float4*)(g_k + (size_t)node * 256 + h * 128 + cq);
            k0 = kp[0]; k1 = kp[1];
            const float4* pp = (const float4*)(prev + (size_t)node * 256 + h * 128 + cq);
            p0 = pp[0]; p1 = pp[1];
        }
        __syncthreads();
        *(float4*)&ksS[ln][cq]     = k0;
        *(float4*)&ksS[ln][cq + 4] = k1;
        *(float4*)&pvS[ln][cq]     = p0;
        *(float4*)&pvS[ln][cq + 4] = p1;
        __syncthreads();
#pragma unroll
        for (int r = 0; r < 16; r++) {
            float a[8], b[8];
#pragma unroll
            for (int i = 0; i < 8; i++) a[i] = ksS[r][tm + i];
#pragma unroll
            for (int j = 0; j < 8; j++) b[j] = pvS[r][tn + j];
#pragma unroll
            for (int i = 0; i < 8; i++)
#pragma unroll
                for (int j = 0; j < 8; j++) acc[i][j] += a[i] * b[j];
        }
#pragma unroll
        for (int r = 0; r < 8; r++) colsum += pvS[rb + r][myc];
    }
    atomicAdd(&g_vssum[h * 128 + myc], colsum);
    float* kv = g_kvs + h * 16384;
#pragma unroll
    for (int i = 0; i < 8; i++)
#pragma unroll
        for (int j = 0; j < 8; j++)
            atomicAdd(&kv[(tm + i) * 128 + tn + j], acc[i][j]);
}

// ---------------- next = (qs @ kvs + vs_sum) / den  (attn term) ----------------
__global__ void qkv_combine_kernel(float* __restrict__ nxt, int n) {
    int h = blockIdx.y;
    __shared__ float As[16][128];
    __shared__ float Bs[16][128];
    int t = threadIdx.x;
    int bm0 = blockIdx.x * 128;
    int am = t >> 1, akq = (t & 1) * 8;
    int bk = t >> 4, bnq = (t & 15) * 8;
    int tm = (t >> 4) * 8, tn = (t & 15) * 8;
    const float* Bmat = g_kvs + h * 16384;
    float acc[8][8];
#pragma unroll
    for (int i = 0; i < 8; i++)
#pragma unroll
        for (int j = 0; j < 8; j++) acc[i][j] = 0.f;

    for (int k0 = 0; k0 < 128; k0 += 16) {
        float4 a0 = make_float4(0, 0, 0, 0), a1 = a0;
        int row = bm0 + am;
        if (row < n) {
            const float4* ap = (const float4*)(g_q + (size_t)row * 256 + h * 128 + k0 + akq);
            a0 = ap[0]; a1 = ap[1];
        }
        const float4* bp = (const float4*)(Bmat + (size_t)(k0 + bk) * 128 + bnq);
        float4 b0 = bp[0], b1 = bp[1];
        __syncthreads();
        As[akq + 0][am] = a0.x; As[akq + 1][am] = a0.y;
        As[akq + 2][am] = a0.z; As[akq + 3][am] = a0.w;
        As[akq + 4][am] = a1.x; As[akq + 5][am] = a1.y;
        As[akq + 6][am] = a1.z; As[akq + 7][am] = a1.w;
        *(float4*)&Bs[bk][bnq]     = b0;
        *(float4*)&Bs[bk][bnq + 4] = b1;
        __syncthreads();
#pragma unroll
        for (int kk = 0; kk < 16; kk++) {
            float a[8], b[8];
#pragma unroll
            for (int i = 0; i < 8; i++) a[i] = As[kk][tm + i];
#pragma unroll
            for (int j = 0; j < 8; j++) b[j] = Bs[kk][tn + j];
#pragma unroll
            for (int i = 0; i < 8; i++)
#pragma unroll
                for (int j = 0; j < 8; j++) acc[i][j] += a[i] * b[j];
        }
    }
#pragma unroll
    for (int i = 0; i < 8; i++) {
        int row = bm0 + tm + i;
        if (row >= n) break;
        float invd = 1.0f / g_den[row * 2 + h];
        float4 o0, o1;
        o0.x = (acc[i][0] + g_vssum[h * 128 + tn + 0]) * invd;
        o0.y = (acc[i][1] + g_vssum[h * 128 + tn + 1]) * invd;
        o0.z = (acc[i][2] + g_vssum[h * 128 + tn + 2]) * invd;
        o0.w = (acc[i][3] + g_vssum[h * 128 + tn + 3]) * invd;
        o1.x = (acc[i][4] + g_vssum[h * 128 + tn + 4]) * invd;
        o1.y = (acc[i][5] + g_vssum[h * 128 + tn + 5]) * invd;
        o1.z = (acc[i][6] + g_vssum[h * 128 + tn + 6]) * invd;
        o1.w = (acc[i][7] + g_vssum[h * 128 + tn + 7]) * invd;
        *(float4*)&nxt[(size_t)row * 256 + h * 128 + tn]     = o0;
        *(float4*)&nxt[(size_t)row * 256 + h * 128 + tn + 4] = o1;
    }
}

// ---------------- GCN: next[dst] += 0.5*deginv[dst] * sum_{src in CSR} prev[src] ----------------
__global__ void gcn_gather_kernel(float* __restrict__ nxt, const float* __restrict__ prev, int n) {
    int gw = (blockIdx.x * blockDim.x + threadIdx.x) >> 5;
    int lane = threadIdx.x & 31;
    if (gw >= n) return;
    int beg = g_csroff[gw], end = g_csroff[gw + 1];
    float s = 0.5f * g_deginv[gw];
    float4 a0 = make_float4(0, 0, 0, 0), a1 = a0;
    for (int e = beg; e < end; e++) {
        int src = g_csrrow[e];
        const float4* p = (const float4*)(prev + (size_t)src * 256);
        float4 v0 = p[lane], v1 = p[lane + 32];
        a0.x += v0.x; a0.y += v0.y; a0.z += v0.z; a0.w += v0.w;
        a1.x += v1.x; a1.y += v1.y; a1.z += v1.z; a1.w += v1.w;
    }
    float4* q = (float4*)(nxt + (size_t)gw * 256);
    float4 o0 = q[lane];
    o0.x += s * a0.x; o0.y += s * a0.y; o0.z += s * a0.z; o0.w += s * a0.w;
    q[lane] = o0;
    float4 o1 = q[lane + 32];
    o1.x += s * a1.x; o1.y += s * a1.y; o1.z += s * a1.z; o1.w += s * a1.w;
    q[lane + 32] = o1;
}

// ---------------- out += 0.5 * term_k @ Wo_slice(k) : [N,256]@[256,128] ----------------
__global__ void out_accum_kernel(const float* __restrict__ term, const float* __restrict__ Wo,
                                 float* __restrict__ out, int n, int ksl) {
    __shared__ float As[16][128];
    __shared__ float Bs[16][128];
    int t = threadIdx.x;
    int bm0 = blockIdx.x * 128;
    int am = t >> 1, akq = (t & 1) * 8;
    int bk = t >> 4, bnq = (t & 15) * 8;
    int tm = (t >> 4) * 8, tn = (t & 15) * 8;
    float acc[8][8];
#pragma unroll
    for (int i = 0; i < 8; i++)
#pragma unroll
        for (int j = 0; j < 8; j++) acc[i][j] = 0.f;

    for (int k0 = 0; k0 < 256; k0 += 16) {
        float4 a0 = make_float4(0, 0, 0, 0), a1 = a0;
        int row = bm0 + am;
        if (row < n) {
            const float4* ap = (const float4*)(term + (size_t)row * 256 + k0 + akq);
            a0 = ap[0]; a1 = ap[1];
        }
        int rg = k0 + bk;
        int wrow = ((rg >> 7) * 640) + ksl * 128 + (rg & 127);
        const float4* bp = (const float4*)(Wo + (size_t)wrow * 128 + bnq);
        float4 b0 = bp[0], b1 = bp[1];
        __syncthreads();
        As[akq + 0][am] = a0.x; As[akq + 1][am] = a0.y;
        As[akq + 2][am] = a0.z; As[akq + 3][am] = a0.w;
        As[akq + 4][am] = a1.x; As[akq + 5][am] = a1.y;
        As[akq + 6][am] = a1.z; As[akq + 7][am] = a1.w;
        *(float4*)&Bs[bk][bnq]     = b0;
        *(float4*)&Bs[bk][bnq + 4] = b1;
        __syncthreads();
#pragma unroll
        for (int kk = 0; kk < 16; kk++) {
            float a[8], b[8];
#pragma unroll
            for (int i = 0; i < 8; i++) a[i] = As[kk][tm + i];
#pragma unroll
            for (int j = 0; j < 8; j++) b[j] = Bs[kk][tn + j];
#pragma unroll
            for (int i = 0; i < 8; i++)
#pragma unroll
                for (int j = 0; j < 8; j++) acc[i][j] += a[i] * b[j];
        }
    }
#pragma unroll
    for (int i = 0; i < 8; i++) {
        int row = bm0 + tm + i;
        if (row >= n) break;
        float4 c0 = *(float4*)&out[(size_t)row * 128 + tn];
        float4 c1 = *(float4*)&out[(size_t)row * 128 + tn + 4];
        c0.x += 0.5f * acc[i][0]; c0.y += 0.5f * acc[i][1];
        c0.z += 0.5f * acc[i][2]; c0.w += 0.5f * acc[i][3];
        c1.x += 0.5f * acc[i][4]; c1.y += 0.5f * acc[i][5];
        c1.z += 0.5f * acc[i][6]; c1.w += 0.5f * acc[i][7];
        *(float4*)&out[(size_t)row * 128 + tn]     = c0;
        *(float4*)&out[(size_t)row * 128 + tn + 4] = c1;
    }
}

// ---------------- host orchestration ----------------
extern "C" void kernel_launch(void* const* d_in, const int* in_sizes, int n_in,
                              void* d_out, int out_size) {
    const float* x   = (const float*)d_in[0];
    const void*  ei  = d_in[1];
    const float* Wqw = (const float*)d_in[2];
    const float* Wqb = (const float*)d_in[3];
    const float* Wkw = (const float*)d_in[4];
    const float* Wkb = (const float*)d_in[5];
    const float* Wow = (const float*)d_in[6];
    const float* Wob = (const float*)d_in[7];
    float* out = (float*)d_out;

    int n = in_sizes[0] / CC;
    int E = in_sizes[1] / 2;

    void *pDeg, *pKvs, *pVs, *pKs, *pA, *pB;
    cudaGetSymbolAddress(&pDeg, g_deg);
    cudaGetSymbolAddress(&pKvs, g_kvs);
    cudaGetSymbolAddress(&pVs,  g_vssum);
    cudaGetSymbolAddress(&pKs,  g_kssum);
    cudaGetSymbolAddress(&pA,   g_bufA);
    cudaGetSymbolAddress(&pB,   g_bufB);

    // ---- edge dtype detect + graph structure + loop-invariants ----
    detect_dtype_kernel<<<1, 256>>>((const int*)ei, in_sizes[1]);
    cudaMemsetAsync(pDeg, 0, (size_t)n * sizeof(int));
    cudaMemsetAsync(pKs,  0, (size_t)HH * CC * sizeof(float));
    edge_deg_kernel<<<(E + 255) / 256, 256>>>(ei, E);
    scan_kernel<<<1, 1024>>>(n, E);
    csr_scatter_kernel<<<(E + 255) / 256, 256>>>(ei, E);

    dim3 gqk((n + 127) / 128, 4);
    qk_gemm_kernel<<<gqk, 256>>>(x, Wqw, Wqb, Wkw, Wkb, n);
    normalize_kernel<<<(n * 4 * 32 + 255) / 256, 256>>>(n);
    kssum_kernel<<<(n + 511) / 512, 256>>>(n);
    den_kernel<<<(n * 2 * 32 + 255) / 256, 256>>>(n);

    broadcast_kernel<<<(n * 256 + 255) / 256, 256>>>(x, n);
    out_init_kernel<<<(n + 127) / 128, 256>>>(x, Wow, Wob, out, n);

    // ---- K_ORDER iterations ----
    float* prev = (float*)pA;
    float* nxt  = (float*)pB;
    for (int ksl = 1; ksl <= 4; ksl++) {
        cudaMemsetAsync(pKvs, 0, (size_t)HH * CC * CC * sizeof(float));
        cudaMemsetAsync(pVs,  0, (size_t)HH * CC * sizeof(float));
        kvs_reduce_kernel<<<dim3((n + 511) / 512, 2), 256>>>(prev, n);
        qkv_combine_kernel<<<dim3((n + 127) / 128, 2), 256>>>(nxt, n);
        gcn_gather_kernel<<<(n * 32 + 255) / 256, 256>>>(nxt, prev, n);
        out_accum_kernel<<<(n + 127) / 128, 256>>>(nxt, Wow, out, n, ksl);
        float* tmp = prev; prev = nxt; nxt = tmp;
    }
}

// round 3
// speedup vs baseline: 1.2754x; 1.2754x over previous
#include <cuda_runtime.h>
#include <cstdint>

#define CC   128
#define HH   2
#define HC   256
#define NMAX 100000
#define EMAX 1600000

// ---------------- device scratch (static, no allocation) ----------------
__device__ float g_q[(size_t)NMAX * HC];      // normalized qs, [n][h][c]
__device__ float g_k[(size_t)NMAX * HC];      // normalized ks
__device__ float g_bufA[(size_t)NMAX * HC];   // term ping
__device__ float g_bufB[(size_t)NMAX * HC];   // term pong
__device__ float g_deginv[NMAX];
__device__ int   g_deg[NMAX];
__device__ int   g_csroff[NMAX + 1];
__device__ int   g_csrcur[NMAX];
__device__ int   g_csrrow[EMAX];
__device__ float g_den[NMAX * HH];
__device__ float g_kvs[HH * CC * CC];
__device__ float g_vssum[HH * CC];
__device__ float g_kssum[HH * CC];
__device__ int   g_is64;

// ---------------- helpers ----------------
__device__ __forceinline__ uint32_t f2tf(float x) {
    uint32_t r;
    asm("cvt.rna.tf32.f32 %0, %1;" : "=r"(r) : "f"(x));
    return r;
}

// m16n8k8 tf32 mma over a 16-deep k tile in smem (k-major [16][128] layout).
// Warp computes a 64x32 patch at (m0, n0). acc[mt][nt][4].
__device__ __forceinline__ void ktile_mma(const uint32_t (*As)[128], const uint32_t (*Bs)[128],
                                          int m0, int n0, int lane, float acc[4][4][4]) {
#pragma unroll
    for (int ks = 0; ks < 2; ks++) {
        int ar = ks * 8 + (lane & 3);
        int ac = lane >> 2;
        uint32_t a[4][4], b[4][2];
#pragma unroll
        for (int mt = 0; mt < 4; mt++) {
            int m = m0 + mt * 16 + ac;
            a[mt][0] = As[ar][m];
            a[mt][1] = As[ar][m + 8];
            a[mt][2] = As[ar + 4][m];
            a[mt][3] = As[ar + 4][m + 8];
        }
#pragma unroll
        for (int nt = 0; nt < 4; nt++) {
            int nn = n0 + nt * 8 + ac;
            b[nt][0] = Bs[ar][nn];
            b[nt][1] = Bs[ar + 4][nn];
        }
#pragma unroll
        for (int mt = 0; mt < 4; mt++)
#pragma unroll
            for (int nt = 0; nt < 4; nt++)
                asm volatile(
                    "mma.sync.aligned.m16n8k8.row.col.f32.tf32.tf32.f32 "
                    "{%0,%1,%2,%3},{%4,%5,%6,%7},{%8,%9},{%0,%1,%2,%3};"
                    : "+f"(acc[mt][nt][0]), "+f"(acc[mt][nt][1]),
                      "+f"(acc[mt][nt][2]), "+f"(acc[mt][nt][3])
                    : "r"(a[mt][0]), "r"(a[mt][1]), "r"(a[mt][2]), "r"(a[mt][3]),
                      "r"(b[nt][0]), "r"(b[nt][1]));
    }
}

// ---------------- edge dtype detection ----------------
__global__ void detect_dtype_kernel(const int* __restrict__ ei32, int twoE) {
    __shared__ int nz;
    if (threadIdx.x == 0) nz = 0;
    __syncthreads();
    int samples = min(1024, twoE / 2);
    int local = 0;
    for (int i = threadIdx.x; i < samples; i += blockDim.x)
        if (ei32[2 * i + 1] != 0) local++;
    if (local) atomicAdd(&nz, local);
    __syncthreads();
    if (threadIdx.x == 0) g_is64 = (nz == 0) ? 1 : 0;
}

__device__ __forceinline__ int edge_col(const void* ei, int E, int e) {
    if (g_is64) return (int)((const long long*)ei)[(size_t)E + e];
    return ((const int*)ei)[E + e];
}
__device__ __forceinline__ int edge_row(const void* ei, int E, int e) {
    if (g_is64) return (int)((const long long*)ei)[e];
    return ((const int*)ei)[e];
}

// ---------------- edge prep ----------------
__global__ void edge_deg_kernel(const void* __restrict__ ei, int E) {
    int e = blockIdx.x * blockDim.x + threadIdx.x;
    if (e < E) atomicAdd(&g_deg[edge_col(ei, E, e)], 1);
}

__global__ void scan_kernel(int n, int E) {
    __shared__ int sh[1024];
    __shared__ int carrySh;
    if (threadIdx.x == 0) carrySh = 0;
    __syncthreads();
    for (int base = 0; base < n; base += 1024) {
        int i = base + threadIdx.x;
        int v = (i < n) ? g_deg[i] : 0;
        sh[threadIdx.x] = v;
        __syncthreads();
        for (int off = 1; off < 1024; off <<= 1) {
            int t = (threadIdx.x >= off) ? sh[threadIdx.x - off] : 0;
            __syncthreads();
            sh[threadIdx.x] += t;
            __syncthreads();
        }
        int excl = sh[threadIdx.x] - v + carrySh;
        if (i < n) {
            g_csroff[i] = excl;
            g_csrcur[i] = excl;
            g_deginv[i] = (v > 0) ? 1.0f / (float)v : 0.0f;
        }
        __syncthreads();
        if (threadIdx.x == 0) carrySh += sh[1023];
        __syncthreads();
    }
    if (threadIdx.x == 0) g_csroff[n] = E;
}

__global__ void csr_scatter_kernel(const void* __restrict__ ei, int E) {
    int e = blockIdx.x * blockDim.x + threadIdx.x;
    if (e < E) {
        int c = edge_col(ei, E, e);
        int pos = atomicAdd(&g_csrcur[c], 1);
        g_csrrow[pos] = edge_row(ei, E, e);
    }
}

// ---------------- q/k projection GEMM (tf32): [N,128] @ [128,512] ----------------
__global__ void __launch_bounds__(256) qk_gemm_kernel(const float* __restrict__ x,
                               const float* __restrict__ Wq, const float* __restrict__ Wqb,
                               const float* __restrict__ Wk, const float* __restrict__ Wkb,
                               int n) {
    __shared__ uint32_t As[16][128];
    __shared__ uint32_t Bs[16][128];
    int t = threadIdx.x;
    int lane = t & 31, wid = t >> 5;
    int m0 = (wid & 1) * 64, n0 = (wid >> 1) * 32;
    int bm0 = blockIdx.x * 128;
    int by = blockIdx.y;
    const float* B   = (by < 2) ? Wq  : Wk;
    const float* bia = (by < 2) ? Wqb : Wkb;
    float*       dst = (by < 2) ? g_q : g_k;
    int coff = (by & 1) * 128;
    int am = t >> 1, akq = (t & 1) * 8;
    int bk = t >> 4, bnq = (t & 15) * 8;
    float acc[4][4][4];
#pragma unroll
    for (int i = 0; i < 4; i++)
#pragma unroll
        for (int j = 0; j < 4; j++)
#pragma unroll
            for (int r = 0; r < 4; r++) acc[i][j][r] = 0.f;

    for (int k0 = 0; k0 < 128; k0 += 16) {
        float4 a0 = make_float4(0, 0, 0, 0), a1 = a0;
        int row = bm0 + am;
        if (row < n) {
            const float4* ap = (const float4*)(x + (size_t)row * 128 + k0 + akq);
            a0 = ap[0]; a1 = ap[1];
        }
        const float4* bp = (const float4*)(B + (size_t)(k0 + bk) * 256 + coff + bnq);
        float4 b0 = bp[0], b1 = bp[1];
        __syncthreads();
        As[akq + 0][am] = f2tf(a0.x); As[akq + 1][am] = f2tf(a0.y);
        As[akq + 2][am] = f2tf(a0.z); As[akq + 3][am] = f2tf(a0.w);
        As[akq + 4][am] = f2tf(a1.x); As[akq + 5][am] = f2tf(a1.y);
        As[akq + 6][am] = f2tf(a1.z); As[akq + 7][am] = f2tf(a1.w);
        Bs[bk][bnq + 0] = f2tf(b0.x); Bs[bk][bnq + 1] = f2tf(b0.y);
        Bs[bk][bnq + 2] = f2tf(b0.z); Bs[bk][bnq + 3] = f2tf(b0.w);
        Bs[bk][bnq + 4] = f2tf(b1.x); Bs[bk][bnq + 5] = f2tf(b1.y);
        Bs[bk][bnq + 6] = f2tf(b1.z); Bs[bk][bnq + 7] = f2tf(b1.w);
        __syncthreads();
        ktile_mma(As, Bs, m0, n0, lane, acc);
    }
#pragma unroll
    for (int mt = 0; mt < 4; mt++) {
        int row = bm0 + m0 + mt * 16 + (lane >> 2);
#pragma unroll
        for (int nt = 0; nt < 4; nt++) {
            int col = coff + n0 + nt * 8 + 2 * (lane & 3);
            float bx = bia[col], by2 = bia[col + 1];
            if (row < n) {
                float2 v = make_float2(acc[mt][nt][0] + bx, acc[mt][nt][1] + by2);
                *(float2*)&dst[(size_t)row * 256 + col] = v;
            }
            if (row + 8 < n) {
                float2 v = make_float2(acc[mt][nt][2] + bx, acc[mt][nt][3] + by2);
                *(float2*)&dst[(size_t)(row + 8) * 256 + col] = v;
            }
        }
    }
}

// ---------------- per-(node,head) L2 normalize (q and k) ----------------
__global__ void normalize_kernel(int n) {
    int gw = (blockIdx.x * blockDim.x + threadIdx.x) >> 5;
    int lane = threadIdx.x & 31;
    if (gw >= n * 4) return;
    int node = gw >> 2, sel = gw & 3;
    float* base = ((sel < 2) ? g_q : g_k) + (size_t)node * 256 + (sel & 1) * 128;
    float4 v = ((float4*)base)[lane];
    float ss = v.x * v.x + v.y * v.y + v.z * v.z + v.w * v.w;
#pragma unroll
    for (int o = 16; o; o >>= 1) ss += __shfl_xor_sync(0xffffffffu, ss, o);
    float inv = rsqrtf(ss);
    v.x *= inv; v.y *= inv; v.z *= inv; v.w *= inv;
    ((float4*)base)[lane] = v;
}

// ---------------- ks_sum (loop-invariant) ----------------
__global__ void kssum_kernel(int n) {
    int col = threadIdx.x;  // 0..255
    int start = blockIdx.x * 512;
    int end = min(start + 512, n);
    float s = 0.f;
    for (int node = start; node < end; node++) s += g_k[(size_t)node * 256 + col];
    atomicAdd(&g_kssum[col], s);
}

// ---------------- den = qs . ks_sum + n (loop-invariant) ----------------
__global__ void den_kernel(int n) {
    int gw = (blockIdx.x * blockDim.x + threadIdx.x) >> 5;
    int lane = threadIdx.x & 31;
    if (gw >= n * 2) return;
    int node = gw >> 1, h = gw & 1;
    float4 qv = ((const float4*)(g_q + (size_t)node * 256 + h * 128))[lane];
    float4 kv = ((const float4*)(g_kssum + h * 128))[lane];
    float d = qv.x * kv.x + qv.y * kv.y + qv.z * kv.z + qv.w * kv.w;
#pragma unroll
    for (int o = 16; o; o >>= 1) d += __shfl_xor_sync(0xffffffffu, d, o);
    if (lane == 0) g_den[node * 2 + h] = d + (float)n;
}

// ---------------- term0 = broadcast x over heads ----------------
__global__ void broadcast_kernel(const float* __restrict__ x, int n) {
    int idx = blockIdx.x * blockDim.x + threadIdx.x;
    if (idx < n * 256) {
        int node = idx >> 8;
        int c = idx & 127;
        g_bufA[idx] = x[(size_t)node * 128 + c];
    }
}

// ---------------- out init (tf32): 0.5*(x @ (Wo[h0,k0]+Wo[h1,k0]) + b) ----------------
__global__ void __launch_bounds__(256) out_init_kernel(const float* __restrict__ x, const float* __restrict__ Wo,
                                const float* __restrict__ Wob, float* __restrict__ out, int n) {
    __shared__ uint32_t As[16][128];
    __shared__ uint32_t Bs[16][128];
    int t = threadIdx.x;
    int lane = t & 31, wid = t >> 5;
    int m0 = (wid & 1) * 64, n0 = (wid >> 1) * 32;
    int bm0 = blockIdx.x * 128;
    int am = t >> 1, akq = (t & 1) * 8;
    int bk = t >> 4, bnq = (t & 15) * 8;
    float acc[4][4][4];
#pragma unroll
    for (int i = 0; i < 4; i++)
#pragma unroll
        for (int j = 0; j < 4; j++)
#pragma unroll
            for (int r = 0; r < 4; r++) acc[i][j][r] = 0.f;

    for (int k0 = 0; k0 < 128; k0 += 16) {
        float4 a0 = make_float4(0, 0, 0, 0), a1 = a0;
        int row = bm0 + am;
        if (row < n) {
            const float4* ap = (const float4*)(x + (size_t)row * 128 + k0 + akq);
            a0 = ap[0]; a1 = ap[1];
        }
        int wr = k0 + bk;
        const float4* p0 = (const float4*)(Wo + (size_t)wr * 128 + bnq);
        const float4* p1 = (const float4*)(Wo + (size_t)(640 + wr) * 128 + bnq);
        float4 u0 = p0[0], u1 = p0[1], v0 = p1[0], v1 = p1[1];
        __syncthreads();
        As[akq + 0][am] = f2tf(a0.x); As[akq + 1][am] = f2tf(a0.y);
        As[akq + 2][am] = f2tf(a0.z); As[akq + 3][am] = f2tf(a0.w);
        As[akq + 4][am] = f2tf(a1.x); As[akq + 5][am] = f2tf(a1.y);
        As[akq + 6][am] = f2tf(a1.z); As[akq + 7][am] = f2tf(a1.w);
        Bs[bk][bnq + 0] = f2tf(u0.x + v0.x); Bs[bk][bnq + 1] = f2tf(u0.y + v0.y);
        Bs[bk][bnq + 2] = f2tf(u0.z + v0.z); Bs[bk][bnq + 3] = f2tf(u0.w + v0.w);
        Bs[bk][bnq + 4] = f2tf(u1.x + v1.x); Bs[bk][bnq + 5] = f2tf(u1.y + v1.y);
        Bs[bk][bnq + 6] = f2tf(u1.z + v1.z); Bs[bk][bnq + 7] = f2tf(u1.w + v1.w);
        __syncthreads();
        ktile_mma(As, Bs, m0, n0, lane, acc);
    }
#pragma unroll
    for (int mt = 0; mt < 4; mt++) {
        int row = bm0 + m0 + mt * 16 + (lane >> 2);
#pragma unroll
        for (int nt = 0; nt < 4; nt++) {
            int col = n0 + nt * 8 + 2 * (lane & 3);
            float bx = Wob[col], by2 = Wob[col + 1];
            if (row < n) {
                float2 v = make_float2(0.5f * (acc[mt][nt][0] + bx), 0.5f * (acc[mt][nt][1] + by2));
                *(float2*)&out[(size_t)row * 128 + col] = v;
            }
            if (row + 8 < n) {
                float2 v = make_float2(0.5f * (acc[mt][nt][2] + bx), 0.5f * (acc[mt][nt][3] + by2));
                *(float2*)&out[(size_t)(row + 8) * 128 + col] = v;
            }
        }
    }
}

// ---------------- kvs[h] += ks_chunk^T @ prev_chunk (tf32) ; vs_sum (fp32) ----------------
__global__ void __launch_bounds__(256) kvs_reduce_kernel(const float* __restrict__ prev, int n) {
    int h = blockIdx.y;
    int c0 = blockIdx.x * 1024;
    int c1 = min(c0 + 1024, n);
    __shared__ uint32_t ksS[16][128];
    __shared__ uint32_t pvS[16][128];
    int t = threadIdx.x;
    int lane = t & 31, wid = t >> 5;
    int m0 = (wid & 1) * 64, n0 = (wid >> 1) * 32;
    int ln = t >> 4;
    int cq = (t & 15) * 8;
    float acc[4][4][4];
#pragma unroll
    for (int i = 0; i < 4; i++)
#pragma unroll
        for (int j = 0; j < 4; j++)
#pragma unroll
            for (int r = 0; r < 4; r++) acc[i][j][r] = 0.f;
    float colsum = 0.f;
    int myc = t & 127, rb = (t >> 7) * 8;

    for (int s = c0; s < c1; s += 16) {
        int node = s + ln;
        float4 z = make_float4(0, 0, 0, 0);
        float4 k0 = z, k1 = z, p0 = z, p1 = z;
        if (node < c1) {
            const float4* kp = (const float4*)(g_k + (size_t)node * 256 + h * 128 + cq);
            k0 = kp[0]; k1 = kp[1];
            const float4* pp = (const float4*)(prev + (size_t)node * 256 + h * 128 + cq);
            p0 = pp[0]; p1 = pp[1];
        }
        __syncthreads();
        ksS[ln][cq + 0] = f2tf(k0.x); ksS[ln][cq + 1] = f2tf(k0.y);
        ksS[ln][cq + 2] = f2tf(k0.z); ksS[ln][cq + 3] = f2tf(k0.w);
        ksS[ln][cq + 4] = f2tf(k1.x); ksS[ln][cq + 5] = f2tf(k1.y);
        ksS[ln][cq + 6] = f2tf(k1.z); ksS[ln][cq + 7] = f2tf(k1.w);
        pvS[ln][cq + 0] = __float_as_uint(p0.x); pvS[ln][cq + 1] = __float_as_uint(p0.y);
        pvS[ln][cq + 2] = __float_as_uint(p0.z); pvS[ln][cq + 3] = __float_as_uint(p0.w);
        pvS[ln][cq + 4] = __float_as_uint(p1.x); pvS[ln][cq + 5] = __float_as_uint(p1.y);
        pvS[ln][cq + 6] = __float_as_uint(p1.z); pvS[ln][cq + 7] = __float_as_uint(p1.w);
        __syncthreads();
        // mma wants tf32 B: convert on the fly is not possible inside fragment load,
        // so round B here too via a second pass view. (B = prev). We convert below.
        // NOTE: fragments read raw f32 bits; HW interprets as tf32 (truncation).
        ktile_mma(ksS, pvS, m0, n0, lane, acc);
#pragma unroll
        for (int r = 0; r < 8; r++) colsum += __uint_as_float(pvS[rb + r][myc]);
    }
    atomicAdd(&g_vssum[h * 128 + myc], colsum);
    float* kv = g_kvs + h * 16384;
#pragma unroll
    for (int mt = 0; mt < 4; mt++) {
        int m = m0 + mt * 16 + (lane >> 2);
#pragma unroll
        for (int nt = 0; nt < 4; nt++) {
            int c = n0 + nt * 8 + 2 * (lane & 3);
            atomicAdd(&kv[m * 128 + c],           acc[mt][nt][0]);
            atomicAdd(&kv[m * 128 + c + 1],       acc[mt][nt][1]);
            atomicAdd(&kv[(m + 8) * 128 + c],     acc[mt][nt][2]);
            atomicAdd(&kv[(m + 8) * 128 + c + 1], acc[mt][nt][3]);
        }
    }
}

// ---------------- next = (qs @ kvs + vs_sum) / den  (tf32) ----------------
__global__ void __launch_bounds__(256) qkv_combine_kernel(float* __restrict__ nxt, int n) {
    int h = blockIdx.y;
    __shared__ uint32_t As[16][128];
    __shared__ uint32_t Bs[16][128];
    int t = threadIdx.x;
    int lane = t & 31, wid = t >> 5;
    int m0 = (wid & 1) * 64, n0 = (wid >> 1) * 32;
    int bm0 = blockIdx.x * 128;
    int am = t >> 1, akq = (t & 1) * 8;
    int bk = t >> 4, bnq = (t & 15) * 8;
    const float* Bmat = g_kvs + h * 16384;
    float acc[4][4][4];
#pragma unroll
    for (int i = 0; i < 4; i++)
#pragma unroll
        for (int j = 0; j < 4; j++)
#pragma unroll
            for (int r = 0; r < 4; r++) acc[i][j][r] = 0.f;

    for (int k0 = 0; k0 < 128; k0 += 16) {
        float4 a0 = make_float4(0, 0, 0, 0), a1 = a0;
        int row = bm0 + am;
        if (row < n) {
            const float4* ap = (const float4*)(g_q + (size_t)row * 256 + h * 128 + k0 + akq);
            a0 = ap[0]; a1 = ap[1];
        }
        const float4* bp = (const float4*)(Bmat + (size_t)(k0 + bk) * 128 + bnq);
        float4 b0 = bp[0], b1 = bp[1];
        __syncthreads();
        As[akq + 0][am] = f2tf(a0.x); As[akq + 1][am] = f2tf(a0.y);
        As[akq + 2][am] = f2tf(a0.z); As[akq + 3][am] = f2tf(a0.w);
        As[akq + 4][am] = f2tf(a1.x); As[akq + 5][am] = f2tf(a1.y);
        As[akq + 6][am] = f2tf(a1.z); As[akq + 7][am] = f2tf(a1.w);
        Bs[bk][bnq + 0] = f2tf(b0.x); Bs[bk][bnq + 1] = f2tf(b0.y);
        Bs[bk][bnq + 2] = f2tf(b0.z); Bs[bk][bnq + 3] = f2tf(b0.w);
        Bs[bk][bnq + 4] = f2tf(b1.x); Bs[bk][bnq + 5] = f2tf(b1.y);
        Bs[bk][bnq + 6] = f2tf(b1.z); Bs[bk][bnq + 7] = f2tf(b1.w);
        __syncthreads();
        ktile_mma(As, Bs, m0, n0, lane, acc);
    }
#pragma unroll
    for (int mt = 0; mt < 4; mt++) {
        int row = bm0 + m0 + mt * 16 + (lane >> 2);
#pragma unroll
        for (int nt = 0; nt < 4; nt++) {
            int col = n0 + nt * 8 + 2 * (lane & 3);
            float vs0 = g_vssum[h * 128 + col], vs1 = g_vssum[h * 128 + col + 1];
            if (row < n) {
                float invd = 1.0f / g_den[row * 2 + h];
                float2 v = make_float2((acc[mt][nt][0] + vs0) * invd,
                                       (acc[mt][nt][1] + vs1) * invd);
                *(float2*)&nxt[(size_t)row * 256 + h * 128 + col] = v;
            }
            if (row + 8 < n) {
                float invd = 1.0f / g_den[(row + 8) * 2 + h];
                float2 v = make_float2((acc[mt][nt][2] + vs0) * invd,
                                       (acc[mt][nt][3] + vs1) * invd);
                *(float2*)&nxt[(size_t)(row + 8) * 256 + h * 128 + col] = v;
            }
        }
    }
}

// ---------------- GCN: next[dst] += 0.5*deginv[dst] * sum_{src in CSR} prev[src] ----------------
__global__ void gcn_gather_kernel(float* __restrict__ nxt, const float* __restrict__ prev, int n) {
    int gw = (blockIdx.x * blockDim.x + threadIdx.x) >> 5;
    int lane = threadIdx.x & 31;
    if (gw >= n) return;
    int beg = g_csroff[gw], end = g_csroff[gw + 1];
    float s = 0.5f * g_deginv[gw];
    float4 a0 = make_float4(0, 0, 0, 0), a1 = a0;
    int e = beg;
    for (; e + 2 <= end; e += 2) {
        int s0 = g_csrrow[e], s1 = g_csrrow[e + 1];
        const float4* p0 = (const float4*)(prev + (size_t)s0 * 256);
        const float4* p1 = (const float4*)(prev + (size_t)s1 * 256);
        float4 u0 = p0[lane], u1 = p0[lane + 32];
        float4 w0 = p1[lane], w1 = p1[lane + 32];
        a0.x += u0.x + w0.x; a0.y += u0.y + w0.y; a0.z += u0.z + w0.z; a0.w += u0.w + w0.w;
        a1.x += u1.x + w1.x; a1.y += u1.y + w1.y; a1.z += u1.z + w1.z; a1.w += u1.w + w1.w;
    }
    if (e < end) {
        int s0 = g_csrrow[e];
        const float4* p0 = (const float4*)(prev + (size_t)s0 * 256);
        float4 u0 = p0[lane], u1 = p0[lane + 32];
        a0.x += u0.x; a0.y += u0.y; a0.z += u0.z; a0.w += u0.w;
        a1.x += u1.x; a1.y += u1.y; a1.z += u1.z; a1.w += u1.w;
    }
    float4* q = (float4*)(nxt + (size_t)gw * 256);
    float4 o0 = q[lane];
    o0.x += s * a0.x; o0.y += s * a0.y; o0.z += s * a0.z; o0.w += s * a0.w;
    q[lane] = o0;
    float4 o1 = q[lane + 32];
    o1.x += s * a1.x; o1.y += s * a1.y; o1.z += s * a1.z; o1.w += s * a1.w;
    q[lane + 32] = o1;
}

// ---------------- out += 0.5 * term_k @ Wo_slice(k) (tf32) ----------------
__global__ void __launch_bounds__(256) out_accum_kernel(const float* __restrict__ term, const float* __restrict__ Wo,
                                 float* __restrict__ out, int n, int ksl) {
    __shared__ uint32_t As[16][128];
    __shared__ uint32_t Bs[16][128];
    int t = threadIdx.x;
    int lane = t & 31, wid = t >> 5;
    int m0 = (wid & 1) * 64, n0 = (wid >> 1) * 32;
    int bm0 = blockIdx.x * 128;
    int am = t >> 1, akq = (t & 1) * 8;
    int bk = t >> 4, bnq = (t & 15) * 8;
    float acc[4][4][4];
#pragma unroll
    for (int i = 0; i < 4; i++)
#pragma unroll
        for (int j = 0; j < 4; j++)
#pragma unroll
            for (int r = 0; r < 4; r++) acc[i][j][r] = 0.f;

    for (int k0 = 0; k0 < 256; k0 += 16) {
        float4 a0 = make_float4(0, 0, 0, 0), a1 = a0;
        int row = bm0 + am;
        if (row < n) {
            const float4* ap = (const float4*)(term + (size_t)row * 256 + k0 + akq);
            a0 = ap[0]; a1 = ap[1];
        }
        int rg = k0 + bk;
        int wrow = ((rg >> 7) * 640) + ksl * 128 + (rg & 127);
        const float4* bp = (const float4*)(Wo + (size_t)wrow * 128 + bnq);
        float4 b0 = bp[0], b1 = bp[1];
        __syncthreads();
        As[akq + 0][am] = f2tf(a0.x); As[akq + 1][am] = f2tf(a0.y);
        As[akq + 2][am] = f2tf(a0.z); As[akq + 3][am] = f2tf(a0.w);
        As[akq + 4][am] = f2tf(a1.x); As[akq + 5][am] = f2tf(a1.y);
        As[akq + 6][am] = f2tf(a1.z); As[akq + 7][am] = f2tf(a1.w);
        Bs[bk][bnq + 0] = f2tf(b0.x); Bs[bk][bnq + 1] = f2tf(b0.y);
        Bs[bk][bnq + 2] = f2tf(b0.z); Bs[bk][bnq + 3] = f2tf(b0.w);
        Bs[bk][bnq + 4] = f2tf(b1.x); Bs[bk][bnq + 5] = f2tf(b1.y);
        Bs[bk][bnq + 6] = f2tf(b1.z); Bs[bk][bnq + 7] = f2tf(b1.w);
        __syncthreads();
        ktile_mma(As, Bs, m0, n0, lane, acc);
    }
#pragma unroll
    for (int mt = 0; mt < 4; mt++) {
        int row = bm0 + m0 + mt * 16 + (lane >> 2);
#pragma unroll
        for (int nt = 0; nt < 4; nt++) {
            int col = n0 + nt * 8 + 2 * (lane & 3);
            if (row < n) {
                float2 c = *(float2*)&out[(size_t)row * 128 + col];
                c.x += 0.5f * acc[mt][nt][0];
                c.y += 0.5f * acc[mt][nt][1];
                *(float2*)&out[(size_t)row * 128 + col] = c;
            }
            if (row + 8 < n) {
                float2 c = *(float2*)&out[(size_t)(row + 8) * 128 + col];
                c.x += 0.5f * acc[mt][nt][2];
                c.y += 0.5f * acc[mt][nt][3];
                *(float2*)&out[(size_t)(row + 8) * 128 + col] = c;
            }
        }
    }
}

// ---------------- host orchestration ----------------
extern "C" void kernel_launch(void* const* d_in, const int* in_sizes, int n_in,
                              void* d_out, int out_size) {
    const float* x   = (const float*)d_in[0];
    const void*  ei  = d_in[1];
    const float* Wqw = (const float*)d_in[2];
    const float* Wqb = (const float*)d_in[3];
    const float* Wkw = (const float*)d_in[4];
    const float* Wkb = (const float*)d_in[5];
    const float* Wow = (const float*)d_in[6];
    const float* Wob = (const float*)d_in[7];
    float* out = (float*)d_out;

    int n = in_sizes[0] / CC;
    int E = in_sizes[1] / 2;

    void *pDeg, *pKvs, *pVs, *pKs, *pA, *pB;
    cudaGetSymbolAddress(&pDeg, g_deg);
    cudaGetSymbolAddress(&pKvs, g_kvs);
    cudaGetSymbolAddress(&pVs,  g_vssum);
    cudaGetSymbolAddress(&pKs,  g_kssum);
    cudaGetSymbolAddress(&pA,   g_bufA);
    cudaGetSymbolAddress(&pB,   g_bufB);

    // ---- edge dtype detect + graph structure + loop-invariants ----
    detect_dtype_kernel<<<1, 256>>>((const int*)ei, in_sizes[1]);
    cudaMemsetAsync(pDeg, 0, (size_t)n * sizeof(int));
    cudaMemsetAsync(pKs,  0, (size_t)HH * CC * sizeof(float));
    edge_deg_kernel<<<(E + 255) / 256, 256>>>(ei, E);
    scan_kernel<<<1, 1024>>>(n, E);
    csr_scatter_kernel<<<(E + 255) / 256, 256>>>(ei, E);

    dim3 gqk((n + 127) / 128, 4);
    qk_gemm_kernel<<<gqk, 256>>>(x, Wqw, Wqb, Wkw, Wkb, n);
    normalize_kernel<<<(n * 4 * 32 + 255) / 256, 256>>>(n);
    kssum_kernel<<<(n + 511) / 512, 256>>>(n);
    den_kernel<<<(n * 2 * 32 + 255) / 256, 256>>>(n);

    broadcast_kernel<<<(n * 256 + 255) / 256, 256>>>(x, n);
    out_init_kernel<<<(n + 127) / 128, 256>>>(x, Wow, Wob, out, n);

    // ---- K_ORDER iterations ----
    float* prev = (float*)pA;
    float* nxt  = (float*)pB;
    for (int ksl = 1; ksl <= 4; ksl++) {
        cudaMemsetAsync(pKvs, 0, (size_t)HH * CC * CC * sizeof(float));
        cudaMemsetAsync(pVs,  0, (size_t)HH * CC * sizeof(float));
        kvs_reduce_kernel<<<dim3((n + 1023) / 1024, 2), 256>>>(prev, n);
        qkv_combine_kernel<<<dim3((n + 127) / 128, 2), 256>>>(nxt, n);
        gcn_gather_kernel<<<(n * 32 + 255) / 256, 256>>>(nxt, prev, n);
        out_accum_kernel<<<(n + 127) / 128, 256>>>(nxt, Wow, out, n, ksl);
        float* tmp = prev; prev = nxt; nxt = tmp;
    }
}

// round 4
// speedup vs baseline: 1.7786x; 1.3946x over previous
#include <cuda_runtime.h>
#include <cuda_bf16.h>
#include <cstdint>

#define CC   128
#define HH   2
#define HC   256
#define NMAX 100000
#define EMAX 1600000

// ---------------- device scratch (static, no allocation) ----------------
__device__ float g_q[(size_t)NMAX * HC];         // normalized qs fp32
__device__ float g_k[(size_t)NMAX * HC];         // normalized ks fp32
__device__ __nv_bfloat16 g_q16[(size_t)NMAX * HC];
__device__ __nv_bfloat16 g_k16[(size_t)NMAX * HC];
__device__ __nv_bfloat16 g_tA16[(size_t)NMAX * HC];  // term ping (bf16)
__device__ __nv_bfloat16 g_tB16[(size_t)NMAX * HC];  // term pong (bf16)
__device__ float g_deginv[NMAX];
__device__ int   g_deg[NMAX];
__device__ int   g_csroff[NMAX + 1];
__device__ int   g_csrcur[NMAX];
__device__ int   g_csrrow[EMAX];
__device__ float g_den[NMAX * HH];
__device__ float g_kvs[HH * CC * CC];
__device__ float g_vssum[HH * CC];
__device__ float g_kssum[HH * CC];
__device__ int   g_is64;

// ---------------- helpers ----------------
__device__ __forceinline__ uint32_t f2tf(float x) {
    uint32_t r;
    asm("cvt.rna.tf32.f32 %0, %1;" : "=r"(r) : "f"(x));
    return r;
}
__device__ __forceinline__ uint32_t packbf(float lo, float hi) {
    __nv_bfloat162 h2 = __floats2bfloat162_rn(lo, hi);
    return *reinterpret_cast<uint32_t*>(&h2);
}
__device__ __forceinline__ float2 unpackbf(uint32_t u) {
    __nv_bfloat162 h2 = *reinterpret_cast<__nv_bfloat162*>(&u);
    return __bfloat1622float2(h2);
}

// tf32 m16n8k8 over a 16-deep k tile (k-major [16][128]) -- used by tf32 GEMMs
__device__ __forceinline__ void ktile_mma(const uint32_t (*As)[128], const uint32_t (*Bs)[128],
                                          int m0, int n0, int lane, float acc[4][4][4]) {
#pragma unroll
    for (int ks = 0; ks < 2; ks++) {
        int ar = ks * 8 + (lane & 3);
        int ac = lane >> 2;
        uint32_t a[4][4], b[4][2];
#pragma unroll
        for (int mt = 0; mt < 4; mt++) {
            int m = m0 + mt * 16 + ac;
            a[mt][0] = As[ar][m];
            a[mt][1] = As[ar][m + 8];
            a[mt][2] = As[ar + 4][m];
            a[mt][3] = As[ar + 4][m + 8];
        }
#pragma unroll
        for (int nt = 0; nt < 4; nt++) {
            int nn = n0 + nt * 8 + ac;
            b[nt][0] = Bs[ar][nn];
            b[nt][1] = Bs[ar + 4][nn];
        }
#pragma unroll
        for (int mt = 0; mt < 4; mt++)
#pragma unroll
            for (int nt = 0; nt < 4; nt++)
                asm volatile(
                    "mma.sync.aligned.m16n8k8.row.col.f32.tf32.tf32.f32 "
                    "{%0,%1,%2,%3},{%4,%5,%6,%7},{%8,%9},{%0,%1,%2,%3};"
                    : "+f"(acc[mt][nt][0]), "+f"(acc[mt][nt][1]),
                      "+f"(acc[mt][nt][2]), "+f"(acc[mt][nt][3])
                    : "r"(a[mt][0]), "r"(a[mt][1]), "r"(a[mt][2]), "r"(a[mt][3]),
                      "r"(b[nt][0]), "r"(b[nt][1]));
    }
}

// bf16 m16n8k16, smem pair-packed along k: S[k2][m] = (k=2*k2, k=2*k2+1), stride 132
template <int KK2>
__device__ __forceinline__ void ktile_mma16(const uint32_t (*As)[132], const uint32_t (*Bs)[132],
                                            int m0, int n0, int lane, float acc[4][4][4], int ksteps) {
    for (int ks = 0; ks < ksteps; ks++) {
        int ar = ks * 8 + (lane & 3);
        int ac = lane >> 2;
        uint32_t a[4][4], b[4][2];
#pragma unroll
        for (int mt = 0; mt < 4; mt++) {
            int m = m0 + mt * 16 + ac;
            a[mt][0] = As[ar][m];
            a[mt][1] = As[ar][m + 8];
            a[mt][2] = As[ar + 4][m];
            a[mt][3] = As[ar + 4][m + 8];
        }
#pragma unroll
        for (int nt = 0; nt < 4; nt++) {
            int nn = n0 + nt * 8 + ac;
            b[nt][0] = Bs[ar][nn];
            b[nt][1] = Bs[ar + 4][nn];
        }
#pragma unroll
        for (int mt = 0; mt < 4; mt++)
#pragma unroll
            for (int nt = 0; nt < 4; nt++)
                asm volatile(
                    "mma.sync.aligned.m16n8k16.row.col.f32.bf16.bf16.f32 "
                    "{%0,%1,%2,%3},{%4,%5,%6,%7},{%8,%9},{%0,%1,%2,%3};"
                    : "+f"(acc[mt][nt][0]), "+f"(acc[mt][nt][1]),
                      "+f"(acc[mt][nt][2]), "+f"(acc[mt][nt][3])
                    : "r"(a[mt][0]), "r"(a[mt][1]), "r"(a[mt][2]), "r"(a[mt][3]),
                      "r"(b[nt][0]), "r"(b[nt][1]));
    }
}

// ---------------- edge dtype detection ----------------
__global__ void detect_dtype_kernel(const int* __restrict__ ei32, int twoE) {
    __shared__ int nz;
    if (threadIdx.x == 0) nz = 0;
    __syncthreads();
    int samples = min(1024, twoE / 2);
    int local = 0;
    for (int i = threadIdx.x; i < samples; i += blockDim.x)
        if (ei32[2 * i + 1] != 0) local++;
    if (local) atomicAdd(&nz, local);
    __syncthreads();
    if (threadIdx.x == 0) g_is64 = (nz == 0) ? 1 : 0;
}

__device__ __forceinline__ int edge_col(const void* ei, int E, int e) {
    if (g_is64) return (int)((const long long*)ei)[(size_t)E + e];
    return ((const int*)ei)[E + e];
}
__device__ __forceinline__ int edge_row(const void* ei, int E, int e) {
    if (g_is64) return (int)((const long long*)ei)[e];
    return ((const int*)ei)[e];
}

// ---------------- edge prep ----------------
__global__ void edge_deg_kernel(const void* __restrict__ ei, int E) {
    int e = blockIdx.x * blockDim.x + threadIdx.x;
    if (e < E) atomicAdd(&g_deg[edge_col(ei, E, e)], 1);
}

__global__ void scan_kernel(int n, int E) {
    __shared__ int sh[1024];
    __shared__ int carrySh;
    if (threadIdx.x == 0) carrySh = 0;
    __syncthreads();
    for (int base = 0; base < n; base += 1024) {
        int i = base + threadIdx.x;
        int v = (i < n) ? g_deg[i] : 0;
        sh[threadIdx.x] = v;
        __syncthreads();
        for (int off = 1; off < 1024; off <<= 1) {
            int t = (threadIdx.x >= off) ? sh[threadIdx.x - off] : 0;
            __syncthreads();
            sh[threadIdx.x] += t;
            __syncthreads();
        }
        int excl = sh[threadIdx.x] - v + carrySh;
        if (i < n) {
            g_csroff[i] = excl;
            g_csrcur[i] = excl;
            g_deginv[i] = (v > 0) ? 1.0f / (float)v : 0.0f;
        }
        __syncthreads();
        if (threadIdx.x == 0) carrySh += sh[1023];
        __syncthreads();
    }
    if (threadIdx.x == 0) g_csroff[n] = E;
}

__global__ void csr_scatter_kernel(const void* __restrict__ ei, int E) {
    int e = blockIdx.x * blockDim.x + threadIdx.x;
    if (e < E) {
        int c = edge_col(ei, E, e);
        int pos = atomicAdd(&g_csrcur[c], 1);
        g_csrrow[pos] = edge_row(ei, E, e);
    }
}

// ---------------- iter-1 GCN gather from fp32 x: nxt = 0.5*deginv*sum x[src], dup heads ----------------
__global__ void gcn_gather_x_kernel(const float* __restrict__ x, __nv_bfloat16* __restrict__ nxt, int n) {
    int gw = (blockIdx.x * blockDim.x + threadIdx.x) >> 5;
    int lane = threadIdx.x & 31;
    if (gw >= n) return;
    int beg = g_csroff[gw], end = g_csroff[gw + 1];
    float s = 0.5f * g_deginv[gw];
    float4 a = make_float4(0, 0, 0, 0);
    int e = beg;
    for (; e + 4 <= end; e += 4) {
        int s0 = g_csrrow[e], s1 = g_csrrow[e + 1], s2 = g_csrrow[e + 2], s3 = g_csrrow[e + 3];
        float4 v0 = ((const float4*)(x + (size_t)s0 * 128))[lane];
        float4 v1 = ((const float4*)(x + (size_t)s1 * 128))[lane];
        float4 v2 = ((const float4*)(x + (size_t)s2 * 128))[lane];
        float4 v3 = ((const float4*)(x + (size_t)s3 * 128))[lane];
        a.x += (v0.x + v1.x) + (v2.x + v3.x);
        a.y += (v0.y + v1.y) + (v2.y + v3.y);
        a.z += (v0.z + v1.z) + (v2.z + v3.z);
        a.w += (v0.w + v1.w) + (v2.w + v3.w);
    }
    for (; e < end; e++) {
        float4 v0 = ((const float4*)(x + (size_t)g_csrrow[e] * 128))[lane];
        a.x += v0.x; a.y += v0.y; a.z += v0.z; a.w += v0.w;
    }
    uint2 o;
    o.x = packbf(s * a.x, s * a.y);
    o.y = packbf(s * a.z, s * a.w);
    *(uint2*)(nxt + (size_t)gw * 256 + lane * 4)       = o;
    *(uint2*)(nxt + (size_t)gw * 256 + 128 + lane * 4) = o;
}

// ---------------- GCN gather bf16: nxt = 0.5*deginv*sum prev[src] (overwrite) ----------------
__global__ void gcn_gather_kernel(__nv_bfloat16* __restrict__ nxt, const __nv_bfloat16* __restrict__ prev, int n) {
    int gw = (blockIdx.x * blockDim.x + threadIdx.x) >> 5;
    int lane = threadIdx.x & 31;
    if (gw >= n) return;
    int beg = g_csroff[gw], end = g_csroff[gw + 1];
    float s = 0.5f * g_deginv[gw];
    float a[8];
#pragma unroll
    for (int i = 0; i < 8; i++) a[i] = 0.f;
    int e = beg;
    for (; e + 4 <= end; e += 4) {
        uint4 v0 = *(const uint4*)(prev + (size_t)g_csrrow[e]     * 256 + lane * 8);
        uint4 v1 = *(const uint4*)(prev + (size_t)g_csrrow[e + 1] * 256 + lane * 8);
        uint4 v2 = *(const uint4*)(prev + (size_t)g_csrrow[e + 2] * 256 + lane * 8);
        uint4 v3 = *(const uint4*)(prev + (size_t)g_csrrow[e + 3] * 256 + lane * 8);
#pragma unroll
        for (int p = 0; p < 4; p++) {
            uint32_t w0 = (&v0.x)[p], w1 = (&v1.x)[p], w2 = (&v2.x)[p], w3 = (&v3.x)[p];
            float2 f0 = unpackbf(w0), f1 = unpackbf(w1), f2 = unpackbf(w2), f3 = unpackbf(w3);
            a[2 * p]     += (f0.x + f1.x) + (f2.x + f3.x);
            a[2 * p + 1] += (f0.y + f1.y) + (f2.y + f3.y);
        }
    }
    for (; e < end; e++) {
        uint4 v0 = *(const uint4*)(prev + (size_t)g_csrrow[e] * 256 + lane * 8);
#pragma unroll
        for (int p = 0; p < 4; p++) {
            float2 f0 = unpackbf((&v0.x)[p]);
            a[2 * p] += f0.x; a[2 * p + 1] += f0.y;
        }
    }
    uint4 o;
    o.x = packbf(s * a[0], s * a[1]);
    o.y = packbf(s * a[2], s * a[3]);
    o.z = packbf(s * a[4], s * a[5]);
    o.w = packbf(s * a[6], s * a[7]);
    *(uint4*)(nxt + (size_t)gw * 256 + lane * 8) = o;
}

// ---------------- q/k projection GEMM (tf32): [N,128] @ [128,512] ----------------
__global__ void __launch_bounds__(256) qk_gemm_kernel(const float* __restrict__ x,
                               const float* __restrict__ Wq, const float* __restrict__ Wqb,
                               const float* __restrict__ Wk, const float* __restrict__ Wkb,
                               int n) {
    __shared__ uint32_t As[16][128];
    __shared__ uint32_t Bs[16][128];
    int t = threadIdx.x;
    int lane = t & 31, wid = t >> 5;
    int m0 = (wid & 1) * 64, n0 = (wid >> 1) * 32;
    int bm0 = blockIdx.x * 128;
    int by = blockIdx.y;
    const float* B   = (by < 2) ? Wq  : Wk;
    const float* bia = (by < 2) ? Wqb : Wkb;
    float*       dst = (by < 2) ? g_q : g_k;
    int coff = (by & 1) * 128;
    int am = t >> 1, akq = (t & 1) * 8;
    int bk = t >> 4, bnq = (t & 15) * 8;
    float acc[4][4][4];
#pragma unroll
    for (int i = 0; i < 4; i++)
#pragma unroll
        for (int j = 0; j < 4; j++)
#pragma unroll
            for (int r = 0; r < 4; r++) acc[i][j][r] = 0.f;

    for (int k0 = 0; k0 < 128; k0 += 16) {
        float4 a0 = make_float4(0, 0, 0, 0), a1 = a0;
        int row = bm0 + am;
        if (row < n) {
            const float4* ap = (const float4*)(x + (size_t)row * 128 + k0 + akq);
            a0 = ap[0]; a1 = ap[1];
        }
        const float4* bp = (const float4*)(B + (size_t)(k0 + bk) * 256 + coff + bnq);
        float4 b0 = bp[0], b1 = bp[1];
        __syncthreads();
        As[akq + 0][am] = f2tf(a0.x); As[akq + 1][am] = f2tf(a0.y);
        As[akq + 2][am] = f2tf(a0.z); As[akq + 3][am] = f2tf(a0.w);
        As[akq + 4][am] = f2tf(a1.x); As[akq + 5][am] = f2tf(a1.y);
        As[akq + 6][am] = f2tf(a1.z); As[akq + 7][am] = f2tf(a1.w);
        Bs[bk][bnq + 0] = f2tf(b0.x); Bs[bk][bnq + 1] = f2tf(b0.y);
        Bs[bk][bnq + 2] = f2tf(b0.z); Bs[bk][bnq + 3] = f2tf(b0.w);
        Bs[bk][bnq + 4] = f2tf(b1.x); Bs[bk][bnq + 5] = f2tf(b1.y);
        Bs[bk][bnq + 6] = f2tf(b1.z); Bs[bk][bnq + 7] = f2tf(b1.w);
        __syncthreads();
        ktile_mma(As, Bs, m0, n0, lane, acc);
    }
#pragma unroll
    for (int mt = 0; mt < 4; mt++) {
        int row = bm0 + m0 + mt * 16 + (lane >> 2);
#pragma unroll
        for (int nt = 0; nt < 4; nt++) {
            int col = coff + n0 + nt * 8 + 2 * (lane & 3);
            float bx = bia[col], by2 = bia[col + 1];
            if (row < n) {
                float2 v = make_float2(acc[mt][nt][0] + bx, acc[mt][nt][1] + by2);
                *(float2*)&dst[(size_t)row * 256 + col] = v;
            }
            if (row + 8 < n) {
                float2 v = make_float2(acc[mt][nt][2] + bx, acc[mt][nt][3] + by2);
                *(float2*)&dst[(size_t)(row + 8) * 256 + col] = v;
            }
        }
    }
}

// ---------------- normalize (fp32) + write bf16 copies ----------------
__global__ void normalize_kernel(int n) {
    int gw = (blockIdx.x * blockDim.x + threadIdx.x) >> 5;
    int lane = threadIdx.x & 31;
    if (gw >= n * 4) return;
    int node = gw >> 2, sel = gw & 3;
    size_t off = (size_t)node * 256 + (sel & 1) * 128;
    float* base = ((sel < 2) ? g_q : g_k) + off;
    __nv_bfloat16* b16 = ((sel < 2) ? g_q16 : g_k16) + off;
    float4 v = ((float4*)base)[lane];
    float ss = v.x * v.x + v.y * v.y + v.z * v.z + v.w * v.w;
#pragma unroll
    for (int o = 16; o; o >>= 1) ss += __shfl_xor_sync(0xffffffffu, ss, o);
    float inv = rsqrtf(ss);
    v.x *= inv; v.y *= inv; v.z *= inv; v.w *= inv;
    ((float4*)base)[lane] = v;
    uint2 u;
    u.x = packbf(v.x, v.y);
    u.y = packbf(v.z, v.w);
    *(uint2*)(b16 + lane * 4) = u;
}

// ---------------- ks_sum (loop-invariant, fp32) ----------------
__global__ void kssum_kernel(int n) {
    int col = threadIdx.x;  // 0..255
    int start = blockIdx.x * 512;
    int end = min(start + 512, n);
    float s = 0.f;
    for (int node = start; node < end; node++) s += g_k[(size_t)node * 256 + col];
    atomicAdd(&g_kssum[col], s);
}

// ---------------- den = qs . ks_sum + n (loop-invariant, fp32) ----------------
__global__ void den_kernel(int n) {
    int gw = (blockIdx.x * blockDim.x + threadIdx.x) >> 5;
    int lane = threadIdx.x & 31;
    if (gw >= n * 2) return;
    int node = gw >> 1, h = gw & 1;
    float4 qv = ((const float4*)(g_q + (size_t)node * 256 + h * 128))[lane];
    float4 kv = ((const float4*)(g_kssum + h * 128))[lane];
    float d = qv.x * kv.x + qv.y * kv.y + qv.z * kv.z + qv.w * kv.w;
#pragma unroll
    for (int o = 16; o; o >>= 1) d += __shfl_xor_sync(0xffffffffu, d, o);
    if (lane == 0) g_den[node * 2 + h] = d + (float)n;
}

// ---------------- term0 = broadcast x over heads (bf16) ----------------
__global__ void broadcast_kernel(const float* __restrict__ x, int n) {
    int idx = blockIdx.x * blockDim.x + threadIdx.x;
    if (idx < n * 256) {
        int node = idx >> 8;
        int c = idx & 127;
        g_tA16[idx] = __float2bfloat16(x[(size_t)node * 128 + c]);
    }
}

// ---------------- out init (tf32): 0.5*(x @ (Wo[h0,k0]+Wo[h1,k0]) + b) ----------------
__global__ void __launch_bounds__(256) out_init_kernel(const float* __restrict__ x, const float* __restrict__ Wo,
                                const float* __restrict__ Wob, float* __restrict__ out, int n) {
    __shared__ uint32_t As[16][128];
    __shared__ uint32_t Bs[16][128];
    int t = threadIdx.x;
    int lane = t & 31, wid = t >> 5;
    int m0 = (wid & 1) * 64, n0 = (wid >> 1) * 32;
    int bm0 = blockIdx.x * 128;
    int am = t >> 1, akq = (t & 1) * 8;
    int bk = t >> 4, bnq = (t & 15) * 8;
    float acc[4][4][4];
#pragma unroll
    for (int i = 0; i < 4; i++)
#pragma unroll
        for (int j = 0; j < 4; j++)
#pragma unroll
            for (int r = 0; r < 4; r++) acc[i][j][r] = 0.f;

    for (int k0 = 0; k0 < 128; k0 += 16) {
        float4 a0 = make_float4(0, 0, 0, 0), a1 = a0;
        int row = bm0 + am;
        if (row < n) {
            const float4* ap = (const float4*)(x + (size_t)row * 128 + k0 + akq);
            a0 = ap[0]; a1 = ap[1];
        }
        int wr = k0 + bk;
        const float4* p0 = (const float4*)(Wo + (size_t)wr * 128 + bnq);
        const float4* p1 = (const float4*)(Wo + (size_t)(640 + wr) * 128 + bnq);
        float4 u0 = p0[0], u1 = p0[1], v0 = p1[0], v1 = p1[1];
        __syncthreads();
        As[akq + 0][am] = f2tf(a0.x); As[akq + 1][am] = f2tf(a0.y);
        As[akq + 2][am] = f2tf(a0.z); As[akq + 3][am] = f2tf(a0.w);
        As[akq + 4][am] = f2tf(a1.x); As[akq + 5][am] = f2tf(a1.y);
        As[akq + 6][am] = f2tf(a1.z); As[akq + 7][am] = f2tf(a1.w);
        Bs[bk][bnq + 0] = f2tf(u0.x + v0.x); Bs[bk][bnq + 1] = f2tf(u0.y + v0.y);
        Bs[bk][bnq + 2] = f2tf(u0.z + v0.z); Bs[bk][bnq + 3] = f2tf(u0.w + v0.w);
        Bs[bk][bnq + 4] = f2tf(u1.x + v1.x); Bs[bk][bnq + 5] = f2tf(u1.y + v1.y);
        Bs[bk][bnq + 6] = f2tf(u1.z + v1.z); Bs[bk][bnq + 7] = f2tf(u1.w + v1.w);
        __syncthreads();
        ktile_mma(As, Bs, m0, n0, lane, acc);
    }
#pragma unroll
    for (int mt = 0; mt < 4; mt++) {
        int row = bm0 + m0 + mt * 16 + (lane >> 2);
#pragma unroll
        for (int nt = 0; nt < 4; nt++) {
            int col = n0 + nt * 8 + 2 * (lane & 3);
            float bx = Wob[col], by2 = Wob[col + 1];
            if (row < n) {
                float2 v = make_float2(0.5f * (acc[mt][nt][0] + bx), 0.5f * (acc[mt][nt][1] + by2));
                *(float2*)&out[(size_t)row * 128 + col] = v;
            }
            if (row + 8 < n) {
                float2 v = make_float2(0.5f * (acc[mt][nt][2] + bx), 0.5f * (acc[mt][nt][3] + by2));
                *(float2*)&out[(size_t)(row + 8) * 128 + col] = v;
            }
        }
    }
}

// ---------------- kvs[h] += ks^T @ prev (bf16 mma) ; vs_sum (fp32) ----------------
__global__ void __launch_bounds__(256) kvs_reduce_kernel(const __nv_bfloat16* __restrict__ prev, int n) {
    int h = blockIdx.y;
    int c0 = blockIdx.x * 1024;
    int c1 = min(c0 + 1024, n);
    __shared__ uint32_t ksS[16][132];
    __shared__ uint32_t pvS[16][132];
    int t = threadIdx.x;
    int lane = t & 31, wid = t >> 5;
    int m0 = (wid & 1) * 64, n0 = (wid >> 1) * 32;
    float acc[4][4][4];
#pragma unroll
    for (int i = 0; i < 4; i++)
#pragma unroll
        for (int j = 0; j < 4; j++)
#pragma unroll
            for (int r = 0; r < 4; r++) acc[i][j][r] = 0.f;
    float colsum = 0.f;
    int myc = t & 127, hb = (t >> 7) * 8;

    for (int s = c0; s < c1; s += 32) {
        __syncthreads();
#pragma unroll
        for (int i = 0; i < 4; i++) {
            int u = t + 256 * i;
            int nn = u >> 6, m2 = u & 63;
            int nd0 = s + 2 * nn, nd1 = nd0 + 1;
            uint32_t k0 = 0, k1 = 0, p0 = 0, p1 = 0;
            if (nd0 < c1) {
                k0 = *(const uint32_t*)(g_k16 + (size_t)nd0 * 256 + h * 128 + 2 * m2);
                p0 = *(const uint32_t*)(prev  + (size_t)nd0 * 256 + h * 128 + 2 * m2);
            }
            if (nd1 < c1) {
                k1 = *(const uint32_t*)(g_k16 + (size_t)nd1 * 256 + h * 128 + 2 * m2);
                p1 = *(const uint32_t*)(prev  + (size_t)nd1 * 256 + h * 128 + 2 * m2);
            }
            ksS[nn][2 * m2]     = __byte_perm(k0, k1, 0x5410);
            ksS[nn][2 * m2 + 1] = __byte_perm(k0, k1, 0x7632);
            pvS[nn][2 * m2]     = __byte_perm(p0, p1, 0x5410);
            pvS[nn][2 * m2 + 1] = __byte_perm(p0, p1, 0x7632);
        }
        __syncthreads();
        ktile_mma16<16>(ksS, pvS, m0, n0, lane, acc, 2);
#pragma unroll
        for (int r = 0; r < 8; r++) {
            float2 f = unpackbf(pvS[hb + r][myc]);
            colsum += f.x + f.y;
        }
    }
    atomicAdd(&g_vssum[h * 128 + myc], colsum);
    float* kv = g_kvs + h * 16384;
#pragma unroll
    for (int mt = 0; mt < 4; mt++) {
        int m = m0 + mt * 16 + (lane >> 2);
#pragma unroll
        for (int nt = 0; nt < 4; nt++) {
            int c = n0 + nt * 8 + 2 * (lane & 3);
            atomicAdd(&kv[m * 128 + c],           acc[mt][nt][0]);
            atomicAdd(&kv[m * 128 + c + 1],       acc[mt][nt][1]);
            atomicAdd(&kv[(m + 8) * 128 + c],     acc[mt][nt][2]);
            atomicAdd(&kv[(m + 8) * 128 + c + 1], acc[mt][nt][3]);
        }
    }
}

// ---------------- nxt += (qs @ kvs + vs_sum) / den  (bf16 mma, RMW-add) ----------------
__global__ void __launch_bounds__(256) qkv_combine_kernel(__nv_bfloat16* __restrict__ nxt, int n) {
    int h = blockIdx.y;
    __shared__ uint32_t As[32][132];
    __shared__ uint32_t Bs[32][132];
    int t = threadIdx.x;
    int lane = t & 31, wid = t >> 5;
    int m0 = (wid & 1) * 64, n0 = (wid >> 1) * 32;
    int bm0 = blockIdx.x * 128;
    const float* kvp = g_kvs + h * 16384;
    float acc[4][4][4];
#pragma unroll
    for (int i = 0; i < 4; i++)
#pragma unroll
        for (int j = 0; j < 4; j++)
#pragma unroll
            for (int r = 0; r < 4; r++) acc[i][j][r] = 0.f;

#pragma unroll
    for (int kc = 0; kc < 2; kc++) {
        int kb = kc * 64;
        __syncthreads();
#pragma unroll
        for (int i = 0; i < 4; i++) {
            int u = t + 256 * i;
            int row = u >> 3, q = u & 7;
            uint4 v = make_uint4(0, 0, 0, 0);
            if (bm0 + row < n)
                v = *(const uint4*)(g_q16 + (size_t)(bm0 + row) * 256 + h * 128 + kb + q * 8);
            As[q * 4 + 0][row] = v.x; As[q * 4 + 1][row] = v.y;
            As[q * 4 + 2][row] = v.z; As[q * 4 + 3][row] = v.w;
        }
#pragma unroll
        for (int i = 0; i < 16; i++) {
            int u = t + 256 * i;
            int d = u & 127, m2 = u >> 7;
            int m = kb + 2 * m2;
            Bs[m2][d] = packbf(kvp[m * 128 + d], kvp[(m + 1) * 128 + d]);
        }
        __syncthreads();
        ktile_mma16<32>(As, Bs, m0, n0, lane, acc, 4);
    }
#pragma unroll
    for (int mt = 0; mt < 4; mt++) {
        int row = bm0 + m0 + mt * 16 + (lane >> 2);
#pragma unroll
        for (int nt = 0; nt < 4; nt++) {
            int col = n0 + nt * 8 + 2 * (lane & 3);
            float vs0 = g_vssum[h * 128 + col], vs1 = g_vssum[h * 128 + col + 1];
            if (row < n) {
                float invd = 1.0f / g_den[row * 2 + h];
                uint32_t* p = (uint32_t*)(nxt + (size_t)row * 256 + h * 128 + col);
                float2 old = unpackbf(*p);
                *p = packbf(old.x + (acc[mt][nt][0] + vs0) * invd,
                            old.y + (acc[mt][nt][1] + vs1) * invd);
            }
            if (row + 8 < n) {
                float invd = 1.0f / g_den[(row + 8) * 2 + h];
                uint32_t* p = (uint32_t*)(nxt + (size_t)(row + 8) * 256 + h * 128 + col);
                float2 old = unpackbf(*p);
                *p = packbf(old.x + (acc[mt][nt][2] + vs0) * invd,
                            old.y + (acc[mt][nt][3] + vs1) * invd);
            }
        }
    }
}

// ---------------- out += 0.5 * term_k @ Wo_slice(k) (bf16 mma) ----------------
__global__ void __launch_bounds__(256) out_accum_kernel(const __nv_bfloat16* __restrict__ term,
                                 const float* __restrict__ Wo,
                                 float* __restrict__ out, int n, int ksl) {
    __shared__ uint32_t As[32][132];
    __shared__ uint32_t Bs[32][132];
    int t = threadIdx.x;
    int lane = t & 31, wid = t >> 5;
    int m0 = (wid & 1) * 64, n0 = (wid >> 1) * 32;
    int bm0 = blockIdx.x * 128;
    float acc[4][4][4];
#pragma unroll
    for (int i = 0; i < 4; i++)
#pragma unroll
        for (int j = 0; j < 4; j++)
#pragma unroll
            for (int r = 0; r < 4; r++) acc[i][j][r] = 0.f;

#pragma unroll
    for (int kc = 0; kc < 4; kc++) {
        int kb = kc * 64;
        __syncthreads();
#pragma unroll
        for (int i = 0; i < 4; i++) {
            int u = t + 256 * i;
            int row = u >> 3, q = u & 7;
            uint4 v = make_uint4(0, 0, 0, 0);
            if (bm0 + row < n)
                v = *(const uint4*)(term + (size_t)(bm0 + row) * 256 + kb + q * 8);
            As[q * 4 + 0][row] = v.x; As[q * 4 + 1][row] = v.y;
            As[q * 4 + 2][row] = v.z; As[q * 4 + 3][row] = v.w;
        }
#pragma unroll
        for (int i = 0; i < 16; i++) {
            int u = t + 256 * i;
            int c = u & 127, j2 = u >> 7;
            int j = kb + 2 * j2;
            int wrow = ((j >> 7) * 640) + ksl * 128 + (j & 127);
            Bs[j2][c] = packbf(Wo[(size_t)wrow * 128 + c], Wo[(size_t)(wrow + 1) * 128 + c]);
        }
        __syncthreads();
        ktile_mma16<32>(As, Bs, m0, n0, lane, acc, 4);
    }
#pragma unroll
    for (int mt = 0; mt < 4; mt++) {
        int row = bm0 + m0 + mt * 16 + (lane >> 2);
#pragma unroll
        for (int nt = 0; nt < 4; nt++) {
            int col = n0 + nt * 8 + 2 * (lane & 3);
            if (row < n) {
                float2 c = *(float2*)&out[(size_t)row * 128 + col];
                c.x += 0.5f * acc[mt][nt][0];
                c.y += 0.5f * acc[mt][nt][1];
                *(float2*)&out[(size_t)row * 128 + col] = c;
            }
            if (row + 8 < n) {
                float2 c = *(float2*)&out[(size_t)(row + 8) * 128 + col];
                c.x += 0.5f * acc[mt][nt][2];
                c.y += 0.5f * acc[mt][nt][3];
                *(float2*)&out[(size_t)(row + 8) * 128 + col] = c;
            }
        }
    }
}

// ---------------- host orchestration ----------------
extern "C" void kernel_launch(void* const* d_in, const int* in_sizes, int n_in,
                              void* d_out, int out_size) {
    const float* x   = (const float*)d_in[0];
    const void*  ei  = d_in[1];
    const float* Wqw = (const float*)d_in[2];
    const float* Wqb = (const float*)d_in[3];
    const float* Wkw = (const float*)d_in[4];
    const float* Wkb = (const float*)d_in[5];
    const float* Wow = (const float*)d_in[6];
    const float* Wob = (const float*)d_in[7];
    float* out = (float*)d_out;

    int n = in_sizes[0] / CC;
    int E = in_sizes[1] / 2;

    void *pDeg, *pKvs, *pVs, *pKs, *pA16, *pB16;
    cudaGetSymbolAddress(&pDeg, g_deg);
    cudaGetSymbolAddress(&pKvs, g_kvs);
    cudaGetSymbolAddress(&pVs,  g_vssum);
    cudaGetSymbolAddress(&pKs,  g_kssum);
    cudaGetSymbolAddress(&pA16, g_tA16);
    cudaGetSymbolAddress(&pB16, g_tB16);

    // ---- launches 1-5: edge prep; launch 6 = gcn_gather_x (ncu target) ----
    cudaMemsetAsync(pDeg, 0, (size_t)n * sizeof(int));           // 1
    detect_dtype_kernel<<<1, 256>>>((const int*)ei, in_sizes[1]); // 2
    edge_deg_kernel<<<(E + 255) / 256, 256>>>(ei, E);             // 3
    scan_kernel<<<1, 1024>>>(n, E);                               // 4
    csr_scatter_kernel<<<(E + 255) / 256, 256>>>(ei, E);          // 5
    gcn_gather_x_kernel<<<(n * 32 + 255) / 256, 256>>>(x, (__nv_bfloat16*)pB16, n);  // 6 ★

    dim3 gqk((n + 127) / 128, 4);
    qk_gemm_kernel<<<gqk, 256>>>(x, Wqw, Wqb, Wkw, Wkb, n);
    normalize_kernel<<<(n * 4 * 32 + 255) / 256, 256>>>(n);
    cudaMemsetAsync(pKs, 0, (size_t)HH * CC * sizeof(float));
    kssum_kernel<<<(n + 511) / 512, 256>>>(n);
    den_kernel<<<(n * 2 * 32 + 255) / 256, 256>>>(n);
    broadcast_kernel<<<(n * 256 + 255) / 256, 256>>>(x, n);
    out_init_kernel<<<(n + 127) / 128, 256>>>(x, Wow, Wob, out, n);

    // ---- K_ORDER iterations (terms in bf16; gather overwrites, combine adds) ----
    __nv_bfloat16* prev = (__nv_bfloat16*)pA16;
    __nv_bfloat16* nxt  = (__nv_bfloat16*)pB16;
    for (int ksl = 1; ksl <= 4; ksl++) {
        cudaMemsetAsync(pKvs, 0, (size_t)HH * CC * CC * sizeof(float));
        cudaMemsetAsync(pVs,  0, (size_t)HH * CC * sizeof(float));
        kvs_reduce_kernel<<<dim3((n + 1023) / 1024, 2), 256>>>(prev, n);
        if (ksl > 1)  // iter 1 gather already done (from x, fp32-exact) at launch 6
            gcn_gather_kernel<<<(n * 32 + 255) / 256, 256>>>(nxt, prev, n);
        qkv_combine_kernel<<<dim3((n + 127) / 128, 2), 256>>>(nxt, n);
        out_accum_kernel<<<(n + 127) / 128, 256>>>(nxt, Wow, out, n, ksl);
        __nv_bfloat16* tmp = prev; prev = nxt; nxt = tmp;
    }
}